// round 11
// baseline (speedup 1.0000x reference)
#include <cuda_runtime.h>
#include <cstdint>

#define SS   512
#define OUTN 12
#define CTAS 128
#define NTHR 256
#define XCH  64

typedef uint32_t u32;

__device__ __forceinline__ float tanhax(float x) {
    float r; asm("tanh.approx.f32 %0, %1;" : "=f"(r) : "f"(x)); return r;
}
__device__ __forceinline__ float sig_t(float x) { return fmaf(0.5f, tanhax(0.5f * x), 0.5f); }

__device__ __forceinline__ u32 bf16rn(float x) {      // f32 -> bf16 bits (RN)
    u32 u = __float_as_uint(x);
    u += 0x7fffu + ((u >> 16) & 1u);
    return u >> 16;
}
__device__ __forceinline__ u32 pkbf(float lo, float hi) {   // bf16x2: lo in low half
    return bf16rn(lo) | (bf16rn(hi) << 16);
}
__device__ __forceinline__ float bfres(float v) {     // residual after bf16 rounding
    return v - __uint_as_float(bf16rn(v) << 16);
}
// gate-interleaved column n = 4*u + g  ->  global weight row g*64 + u
__device__ __forceinline__ int grow(int n) { return (n & 3) * 64 + (n >> 2); }

__device__ __forceinline__ void mma16(float d[4], const u32 a[4], u32 b0, u32 b1) {
    asm volatile("mma.sync.aligned.m16n8k16.row.col.f32.bf16.bf16.f32 "
                 "{%0,%1,%2,%3}, {%4,%5,%6,%7}, {%8,%9}, {%0,%1,%2,%3};"
                 : "+f"(d[0]), "+f"(d[1]), "+f"(d[2]), "+f"(d[3])
                 : "r"(a[0]), "r"(a[1]), "r"(a[2]), "r"(a[3]), "r"(b0), "r"(b1));
}

// smem float offsets
#define OF_A0    0        // u32 A-frag buf layer0: [2 slot][4 kt][32 lane][4 reg]
#define OF_A1    1024
#define OF_XS    2048     // [XCH][16]
#define OF_HFIN  3072     // [16 b][64 u]
#define OF_SI0   4096     // [w][nt][lane][4]: bias0 n0, bias0 n1, wih0 n0, wih0 n1
#define OF_SI1   8192     // [w][nt][lane][2]: bias1 n0, bias1 n1
#define OF_W1H   10240    // Wih1 hi frag: [w][nt][kt][lane][2] u32
#define OF_L1    18432    // Wih1 lo frag, same shape
#define OF_L0R   26624    // Whh0 lo frag (moved from regs), same shape
#define OF_L2R   34816    // Whh1 lo frag, same shape
#define SMEMF    43008    // 168 KB

__global__ void __launch_bounds__(NTHR, 1) lstm2_bf16(
    const float* __restrict__ x,
    const float* __restrict__ w_ih0, const float* __restrict__ w_hh0,
    const float* __restrict__ b_ih0, const float* __restrict__ b_hh0,
    const float* __restrict__ w_ih1, const float* __restrict__ w_hh1,
    const float* __restrict__ b_ih1, const float* __restrict__ b_hh1,
    const float* __restrict__ fc_w, const float* __restrict__ fc_b,
    float* __restrict__ out)
{
    extern __shared__ float sm[];
    u32*   A0   = (u32*)(sm + OF_A0);
    u32*   A1   = (u32*)(sm + OF_A1);
    float* xs   = sm + OF_XS;
    float* hfin = sm + OF_HFIN;
    float* si0  = sm + OF_SI0;
    float* si1  = sm + OF_SI1;
    u32*   w1h  = (u32*)(sm + OF_W1H);
    u32*   l1f  = (u32*)(sm + OF_L1);
    u32*   l0r  = (u32*)(sm + OF_L0R);
    u32*   l2r  = (u32*)(sm + OF_L2R);

    const int tid  = threadIdx.x;
    const int lane = tid & 31;
    const int w    = tid >> 5;          // warp owns cols [32w, 32w+32)
    const int g    = lane >> 2;
    const int tg   = lane & 3;
    const int evn  = (tg & 1) == 0;
    const int rr   = g + 8 * (tg & 1);  // batch row this lane cells
    const int b0g  = blockIdx.x * 16;

    // ---------------- one-time staging ----------------
    for (int e = tid; e < 2048; e += NTHR) sm[e] = 0.f;   // zero A bufs (h(-1)=0)

    // hi frags for Whh0/Whh1 resident in regs; all lo residuals + Wih1 in smem.
    u32 rh0[4][4][2], rh2[4][4][2];
    const int fb = (w * 512 + lane) * 2;   // per-warp frag base (u32 idx)
#pragma unroll
    for (int nt = 0; nt < 4; nt++) {
        const int n  = w * 32 + nt * 8 + g;
        const int gr = grow(n);
#pragma unroll
        for (int kt = 0; kt < 4; kt++) {
            const int k0 = 16 * kt + 2 * tg;
            const int fo = fb + (nt * 4 + kt) * 64;
            // Whh0
            float v00 = w_hh0[gr * 64 + k0],     v01 = w_hh0[gr * 64 + k0 + 1];
            float v10 = w_hh0[gr * 64 + k0 + 8], v11 = w_hh0[gr * 64 + k0 + 9];
            rh0[nt][kt][0] = pkbf(v00, v01);
            rh0[nt][kt][1] = pkbf(v10, v11);
            l0r[fo + 0] = pkbf(bfres(v00), bfres(v01));
            l0r[fo + 1] = pkbf(bfres(v10), bfres(v11));
            // Whh1
            v00 = w_hh1[gr * 64 + k0];     v01 = w_hh1[gr * 64 + k0 + 1];
            v10 = w_hh1[gr * 64 + k0 + 8]; v11 = w_hh1[gr * 64 + k0 + 9];
            rh2[nt][kt][0] = pkbf(v00, v01);
            rh2[nt][kt][1] = pkbf(v10, v11);
            l2r[fo + 0] = pkbf(bfres(v00), bfres(v01));
            l2r[fo + 1] = pkbf(bfres(v10), bfres(v11));
            // Wih1 -> smem frags
            v00 = w_ih1[gr * 64 + k0];     v01 = w_ih1[gr * 64 + k0 + 1];
            v10 = w_ih1[gr * 64 + k0 + 8]; v11 = w_ih1[gr * 64 + k0 + 9];
            w1h[fo + 0] = pkbf(v00, v01);
            w1h[fo + 1] = pkbf(v10, v11);
            l1f[fo + 0] = pkbf(bfres(v00), bfres(v01));
            l1f[fo + 1] = pkbf(bfres(v10), bfres(v11));
        }
        // bias / input-weight tables for this warp's cols (cols 2tg, 2tg+1 of ntile)
        const int n0 = w * 32 + nt * 8 + 2 * tg, n1 = n0 + 1;
        const int g0 = grow(n0), g1 = grow(n1);
        float* p0 = si0 + (((w * 4 + nt) * 32) + lane) * 4;
        p0[0] = b_ih0[g0] + b_hh0[g0];
        p0[1] = b_ih0[g1] + b_hh0[g1];
        p0[2] = w_ih0[g0];                 // INPUT_SIZE == 1
        p0[3] = w_ih0[g1];
        float* p1 = si1 + (((w * 4 + nt) * 32) + lane) * 2;
        p1[0] = b_ih1[g0] + b_hh1[g0];
        p1[1] = b_ih1[g1] + b_hh1[g1];
    }

    // publish slots: value (row rr, unit u = w*8 + 2nt + uoff) -> frag position
    int pub_idx[4];
#pragma unroll
    for (int nt = 0; nt < 4; nt++) {
        const int kpn = 4 * w + nt;          // unit-pair index in K
        const int kt_ = kpn >> 3, kp8 = kpn & 7;
        const int tgp = kp8 & 3;
        const int lane_ = (rr & 7) * 4 + tgp;
        const int reg = (kp8 >= 4 ? 2 : 0) + (rr >= 8 ? 1 : 0);
        pub_idx[nt] = (kt_ * 32 + lane_) * 4 + reg;
    }

    float c0[4] = {0.f, 0.f, 0.f, 0.f}, c1[4] = {0.f, 0.f, 0.f, 0.f};
    float hv1[4] = {0.f, 0.f, 0.f, 0.f};
    __syncthreads();

    // ---------------- recurrence ----------------
    for (int t = 0; t < SS; t++) {
        if ((t & (XCH - 1)) == 0) {          // refill x chunk [t, t+XCH)
            for (int e = tid; e < 16 * XCH; e += NTHR) {
                int tc = e & (XCH - 1), b = e >> 6;
                xs[tc * 16 + b] = x[(size_t)(b0g + b) * SS + t + tc];
            }
            __syncthreads();
        }
        const int p = t & 1;
        const u32* A0r = A0 + p * 512;
        const u32* A1r = A1 + p * 512;
        u32* A0w = A0 + (p ^ 1) * 512;
        u32* A1w = A1 + (p ^ 1) * 512;

        const int tloc = t & (XCH - 1);
        const float xg  = xs[tloc * 16 + g];
        const float xg8 = xs[tloc * 16 + g + 8];

        // ---- D0 = bias0 + wih0*x_t ;  D1 = bias1 ----
        float D0[4][4], D1[4][4];
#pragma unroll
        for (int nt = 0; nt < 4; nt++) {
            float4 ini = *(const float4*)(si0 + (((w * 4 + nt) * 32) + lane) * 4);
            D0[nt][0] = fmaf(ini.z, xg,  ini.x);
            D0[nt][1] = fmaf(ini.w, xg,  ini.y);
            D0[nt][2] = fmaf(ini.z, xg8, ini.x);
            D0[nt][3] = fmaf(ini.w, xg8, ini.y);
            float2 bi = *(const float2*)(si1 + (((w * 4 + nt) * 32) + lane) * 2);
            D1[nt][0] = bi.x; D1[nt][1] = bi.y;
            D1[nt][2] = bi.x; D1[nt][3] = bi.y;
        }

        // ---- GEMM0 (D0 += Whh0*h0) and GEMM2 (D1 += Whh1*h1), interleaved ----
#pragma unroll
        for (int kt = 0; kt < 4; kt++) {
            u32 a[4], b[4];
            *(uint4*)a = *(const uint4*)(A0r + (kt * 32 + lane) * 4);
            *(uint4*)b = *(const uint4*)(A1r + (kt * 32 + lane) * 4);
#pragma unroll
            for (int nt = 0; nt < 4; nt++) {
                mma16(D0[nt], a, rh0[nt][kt][0], rh0[nt][kt][1]);
                mma16(D1[nt], b, rh2[nt][kt][0], rh2[nt][kt][1]);
            }
#pragma unroll
            for (int nt = 0; nt < 4; nt++) {
                uint2 lp0 = *(const uint2*)(l0r + fb + (nt * 4 + kt) * 64);
                mma16(D0[nt], a, lp0.x, lp0.y);
                uint2 lp2 = *(const uint2*)(l2r + fb + (nt * 4 + kt) * 64);
                mma16(D1[nt], b, lp2.x, lp2.y);
            }
        }

        // ---- cell 0 (warp-local; pair i,f with g,o via shfl_xor 1) ----
        float hv0[4];
#pragma unroll
        for (int nt = 0; nt < 4; nt++) {
            float s0 = evn ? D0[nt][2] : D0[nt][0];
            float s1 = evn ? D0[nt][3] : D0[nt][1];
            float r0 = __shfl_xor_sync(0xffffffffu, s0, 1);
            float r1 = __shfl_xor_sync(0xffffffffu, s1, 1);
            float iv = evn ? D0[nt][0] : r0;
            float fv = evn ? D0[nt][1] : r1;
            float gv = evn ? r0        : D0[nt][2];
            float ov = evn ? r1        : D0[nt][3];
            float cc = fmaf(sig_t(fv), c0[nt], sig_t(iv) * tanhax(gv));
            c0[nt] = cc;
            hv0[nt] = sig_t(ov) * tanhax(cc);
        }
        // publish h0(t) as bf16x2 into alternate buffer (pair units via shfl_xor 2)
#pragma unroll
        for (int nt = 0; nt < 4; nt++) {
            float oth = __shfl_xor_sync(0xffffffffu, hv0[nt], 2);
            if (tg < 2) A0w[pub_idx[nt]] = pkbf(hv0[nt], oth);
        }
        __syncthreads();                     // A: h0(t) visible

        // ---- GEMM1: D1 += Wih1 * h0(t) ----
#pragma unroll
        for (int kt = 0; kt < 4; kt++) {
            u32 a[4];
            *(uint4*)a = *(const uint4*)(A0w + (kt * 32 + lane) * 4);
#pragma unroll
            for (int nt = 0; nt < 4; nt++) {
                uint2 hp = *(const uint2*)(w1h + fb + (nt * 4 + kt) * 64);
                mma16(D1[nt], a, hp.x, hp.y);
                uint2 lp = *(const uint2*)(l1f + fb + (nt * 4 + kt) * 64);
                mma16(D1[nt], a, lp.x, lp.y);
            }
        }

        // ---- cell 1 ----
#pragma unroll
        for (int nt = 0; nt < 4; nt++) {
            float s0 = evn ? D1[nt][2] : D1[nt][0];
            float s1 = evn ? D1[nt][3] : D1[nt][1];
            float r0 = __shfl_xor_sync(0xffffffffu, s0, 1);
            float r1 = __shfl_xor_sync(0xffffffffu, s1, 1);
            float iv = evn ? D1[nt][0] : r0;
            float fv = evn ? D1[nt][1] : r1;
            float gv = evn ? r0        : D1[nt][2];
            float ov = evn ? r1        : D1[nt][3];
            float cc = fmaf(sig_t(fv), c1[nt], sig_t(iv) * tanhax(gv));
            c1[nt] = cc;
            hv1[nt] = sig_t(ov) * tanhax(cc);
        }
#pragma unroll
        for (int nt = 0; nt < 4; nt++) {
            float oth = __shfl_xor_sync(0xffffffffu, hv1[nt], 2);
            if (tg < 2) A1w[pub_idx[nt]] = pkbf(hv1[nt], oth);
        }
        __syncthreads();                     // B: h1(t) visible for next step
    }

    // ---------------- epilogue ----------------
#pragma unroll
    for (int nt = 0; nt < 4; nt++)
        hfin[rr * 64 + (w * 8 + 2 * nt + (tg >> 1))] = hv1[nt];
    __syncthreads();

    for (int idx = tid; idx < 16 * OUTN; idx += NTHR) {
        int b = idx / OUTN, o = idx - b * OUTN;
        float s = fc_b[o];
#pragma unroll 16
        for (int uu = 0; uu < 64; uu++)
            s += hfin[b * 64 + uu] * fc_w[o * 64 + uu];
        out[(size_t)(b0g + b) * OUTN + o] = s;
    }
}

extern "C" void kernel_launch(void* const* d_in, const int* in_sizes, int n_in,
                              void* d_out, int out_size) {
    (void)in_sizes; (void)n_in; (void)out_size;
    const float* x     = (const float*)d_in[0];
    const float* w_ih0 = (const float*)d_in[1];
    const float* w_hh0 = (const float*)d_in[2];
    const float* b_ih0 = (const float*)d_in[3];
    const float* b_hh0 = (const float*)d_in[4];
    const float* w_ih1 = (const float*)d_in[5];
    const float* w_hh1 = (const float*)d_in[6];
    const float* b_ih1 = (const float*)d_in[7];
    const float* b_hh1 = (const float*)d_in[8];
    const float* fc_w  = (const float*)d_in[9];
    const float* fc_b  = (const float*)d_in[10];

    size_t smem = (size_t)SMEMF * sizeof(float);
    cudaFuncSetAttribute(lstm2_bf16, cudaFuncAttributeMaxDynamicSharedMemorySize, (int)smem);
    lstm2_bf16<<<CTAS, NTHR, smem>>>(x, w_ih0, w_hh0, b_ih0, b_hh0,
                                     w_ih1, w_hh1, b_ih1, b_hh1,
                                     fc_w, fc_b, (float*)d_out);
}